// round 5
// baseline (speedup 1.0000x reference)
#include <cuda_runtime.h>
#include <cuda_bf16.h>

// MeanMemoryMessageReducer — segment mean + last timestamp, sorted segment_ids.
//
// 2-kernel pipeline:
//   K1 bounds_scan_v8 : 8 elems/thread (2x int4) transition scan; predecessor
//                       comes from __shfl_up (one scalar LDG per warp only)
//   K2 mean_kernel    : warp-per-segment, float4 streaming loads,
//                       fused epilogue (nids cast + last-timestamp) on lane 0
//
// Output layout (float32): [ nids(M) | means(M*128) | last_ts(M) ]

#define DCOLS 128
#define MAX_M (1 << 20)

__device__ int g_bounds[MAX_M + 1];

// bounds[s] = first index i with seg[i] >= s. For each adjacent pair (p, c),
// all s in (p, c] get bounds[s] = index_of(c). Thread covers [8i, 8i+8).
// Lane l's predecessor value is lane l-1's last element (contiguous coverage),
// fetched via shuffle; only lane 0 loads seg[base-1] from memory.
__global__ __launch_bounds__(256) void bounds_scan_v8(
    const int* __restrict__ seg, int N, int M)
{
    const int i = blockIdx.x * blockDim.x + threadIdx.x;
    const int base = i * 8;
    const int lane = threadIdx.x & 31;
    const bool active = (base < N);
    const int lim = active ? ((base + 8 <= N) ? 8 : (N - base)) : 0;

    int vals[8];
    #pragma unroll
    for (int j = 0; j < 8; ++j) vals[j] = 0;

    if (lim == 8) {
        const int4 v0 = *reinterpret_cast<const int4*>(seg + base);
        const int4 v1 = *reinterpret_cast<const int4*>(seg + base + 4);
        vals[0] = v0.x; vals[1] = v0.y; vals[2] = v0.z; vals[3] = v0.w;
        vals[4] = v1.x; vals[5] = v1.y; vals[6] = v1.z; vals[7] = v1.w;
    } else if (active) {
        for (int j = 0; j < lim; ++j) vals[j] = seg[base + j];
    }

    const int lastv = active ? vals[lim - 1] : 0;

    // All lanes converged here: full-mask shuffle is safe.
    const int from_left = __shfl_up_sync(0xffffffffu, lastv, 1);

    if (!active) return;

    int p;
    if (lane == 0) {
        p = (base == 0) ? -1 : seg[base - 1];
    } else {
        p = from_left;   // lane-1 covers [base-8, base) and is full if we're active
    }

    #pragma unroll
    for (int j = 0; j < 8; ++j) {
        if (j < lim) {
            const int c = vals[j];
            for (int s = p + 1; s <= c; ++s)
                g_bounds[s] = base + j;
            p = c;
        }
    }

    if (base + lim == N) {                  // thread owning the final element
        for (int s = p + 1; s <= M; ++s)
            g_bounds[s] = N;
    }
}

__global__ __launch_bounds__(256) void mean_kernel(
    const float* __restrict__ msgs,
    const int*   __restrict__ nids,
    const float* __restrict__ ts,
    float* __restrict__ out,
    int M, int vec_ok)
{
    const int warp = (int)((blockIdx.x * blockDim.x + threadIdx.x) >> 5);
    const int lane = threadIdx.x & 31;
    if (warp >= M) return;

    const int start = __ldg(&g_bounds[warp]);
    const int end   = __ldg(&g_bounds[warp + 1]);
    const int cnt   = end - start;

    // Fused epilogue: nid cast + last timestamp (ref clips empty-seg idx to 0)
    if (lane == 0) {
        out[warp] = (float)nids[warp];
        const int idx = (cnt > 0) ? (end - 1) : 0;
        out[(size_t)M * (DCOLS + 1) + warp] = ts[idx];
    }

    // Row = 128 floats = 32 float4; lane l owns columns [4l, 4l+4).
    const float4* p = reinterpret_cast<const float4*>(msgs)
                      + (size_t)start * 32 + lane;

    float4 acc = make_float4(0.f, 0.f, 0.f, 0.f);
    int n = cnt;
    while (n >= 4) {                       // 4 independent LDG.128 in flight
        float4 a = __ldcs(p);
        float4 b = __ldcs(p + 32);
        float4 c = __ldcs(p + 64);
        float4 d = __ldcs(p + 96);
        acc.x += (a.x + b.x) + (c.x + d.x);
        acc.y += (a.y + b.y) + (c.y + d.y);
        acc.z += (a.z + b.z) + (c.z + d.z);
        acc.w += (a.w + b.w) + (c.w + d.w);
        p += 128;
        n -= 4;
    }
    while (n > 0) {
        float4 a = __ldcs(p);
        acc.x += a.x; acc.y += a.y; acc.z += a.z; acc.w += a.w;
        p += 32;
        n -= 1;
    }

    const float inv = 1.0f / fmaxf((float)cnt, 1.0f);
    acc.x *= inv; acc.y *= inv; acc.z *= inv; acc.w *= inv;

    float* ob = out + (size_t)M + (size_t)warp * DCOLS + lane * 4;
    if (vec_ok) {
        __stcs(reinterpret_cast<float4*>(ob), acc);
    } else {
        ob[0] = acc.x; ob[1] = acc.y; ob[2] = acc.z; ob[3] = acc.w;
    }
}

extern "C" void kernel_launch(void* const* d_in, const int* in_sizes, int n_in,
                              void* d_out, int out_size)
{
    const int*   nids = (const int*)d_in[0];
    const float* msgs = (const float*)d_in[1];
    const float* ts   = (const float*)d_in[2];
    const int*   seg  = (const int*)d_in[3];
    float* out = (float*)d_out;

    const int M = in_sizes[0];
    const int N = in_sizes[2];
    const int vec_ok = ((M & 3) == 0) ? 1 : 0;   // out+M 16B-aligned

    const int n8 = (N + 7) / 8;
    bounds_scan_v8<<<(n8 + 255) / 256, 256>>>(seg, N, M);

    const long long threads = (long long)M * 32;
    mean_kernel<<<(unsigned)((threads + 255) / 256), 256>>>(
        msgs, nids, ts, out, M, vec_ok);
}